// round 10
// baseline (speedup 1.0000x reference)
#include <cuda_runtime.h>
#include <cuda_bf16.h>
#include <cstdint>

// Problem constants
#define NN      64
#define TT      512
#define BB      64
#define PP      32
#define KDIM    4096        // N*N
#define NCOLS   512         // T

// ---------------------------------------------------------------------------
// Device scratch (static — allocation-free per harness rules)
// g_w is stored TRANSPOSED within each t-slab: g_w[t*4096 + m*64 + n]
// (n fastest) so the gather's warp loads are 128B-coalesced.
// Split operands stored TILED: tile = [128 rows x 32 k] bf16 = 8 KB
// contiguous, SW64-swizzled; GEMM fetches a stage with 4 TMA bulk copies.
// ---------------------------------------------------------------------------
__device__ float g_w[TT * KDIM];
__device__ __nv_bfloat16 g_hi_t[(size_t)KDIM * KDIM];
__device__ __nv_bfloat16 g_lo_t[(size_t)KDIM * KDIM];
__device__ __nv_bfloat16 w2t_hi_t[(size_t)NCOLS * KDIM];
__device__ __nv_bfloat16 w2t_lo_t[(size_t)NCOLS * KDIM];
__device__ float g_Zp[4][BB * NN];                       // gather partials

// ---------------------------------------------------------------------------
// PTX helpers (baseline sm_90-level PTX, valid on plain sm_103 target)
// ---------------------------------------------------------------------------
__device__ __forceinline__ uint32_t smem_u32(const void* p) {
    uint32_t a;
    asm("{ .reg .u64 t; cvta.to.shared.u64 t, %1; cvt.u32.u64 %0, t; }"
        : "=r"(a) : "l"(p));
    return a;
}

__device__ __forceinline__ void cp_bulk8k(uint32_t dst, const void* src,
                                          uint32_t mbar) {
    asm volatile(
        "cp.async.bulk.shared::cluster.global.mbarrier::complete_tx::bytes "
        "[%0], [%1], %2, [%3];"
        :: "r"(dst), "l"(src), "r"(8192u), "r"(mbar) : "memory");
}

__device__ __forceinline__ void mbar_init(uint32_t mbar, uint32_t cnt) {
    asm volatile("mbarrier.init.shared.b64 [%0], %1;" :: "r"(mbar), "r"(cnt)
                 : "memory");
}

__device__ __forceinline__ void mbar_expect_tx(uint32_t mbar, uint32_t bytes) {
    asm volatile("mbarrier.arrive.expect_tx.shared.b64 _, [%0], %1;"
                 :: "r"(mbar), "r"(bytes) : "memory");
}

__device__ __forceinline__ void mbar_wait(uint32_t mbar, uint32_t parity) {
    asm volatile(
        "{\n\t"
        ".reg .pred P1;\n\t"
        "WAIT_LOOP_%=:\n\t"
        "mbarrier.try_wait.parity.acquire.cta.shared::cta.b64 P1, [%0], %1, 0x989680;\n\t"
        "@P1 bra.uni WAIT_DONE_%=;\n\t"
        "bra.uni WAIT_LOOP_%=;\n\t"
        "WAIT_DONE_%=:\n\t"
        "}"
        :: "r"(mbar), "r"(parity) : "memory");
}

#define LDSM4(r, addr)                                                         \
    asm volatile("ldmatrix.sync.aligned.m8n8.x4.shared.b16 "                   \
                 "{%0,%1,%2,%3}, [%4];"                                        \
                 : "=r"((r)[0]), "=r"((r)[1]), "=r"((r)[2]), "=r"((r)[3])      \
                 : "r"(addr))

#define MMA16816(c, a, b0, b1)                                                 \
    asm volatile("mma.sync.aligned.m16n8k16.row.col.f32.bf16.bf16.f32 "        \
                 "{%0,%1,%2,%3},{%4,%5,%6,%7},{%8,%9},{%0,%1,%2,%3};"          \
                 : "+f"((c)[0]), "+f"((c)[1]), "+f"((c)[2]), "+f"((c)[3])      \
                 : "r"((a)[0]), "r"((a)[1]), "r"((a)[2]), "r"((a)[3]),         \
                   "r"(b0), "r"(b1))

// SW64 swizzle for 64-byte rows (conflict-free ldmatrix, proven)
__device__ __forceinline__ uint32_t swz64(uint32_t off) {
    return off ^ ((off >> 3) & 0x30);
}

__device__ __forceinline__ uint32_t pk_hi(float x, float y) {
    return ((uint32_t)__bfloat16_as_ushort(__float2bfloat16(y)) << 16) |
           __bfloat16_as_ushort(__float2bfloat16(x));
}
__device__ __forceinline__ uint32_t pk_lo(float x, float y) {
    const float lx = x - __bfloat162float(__float2bfloat16(x));
    const float ly = y - __bfloat162float(__float2bfloat16(y));
    return pk_hi(lx, ly);
}
__device__ __forceinline__ void pack8(const float4& u, const float4& v,
                                      uint4& h, uint4& l) {
    h.x = pk_hi(u.x, u.y); h.y = pk_hi(u.z, u.w);
    h.z = pk_hi(v.x, v.y); h.w = pk_hi(v.z, v.w);
    l.x = pk_lo(u.x, u.y); l.y = pk_lo(u.z, u.w);
    l.z = pk_lo(v.x, v.y); l.w = pk_lo(v.z, v.w);
}

// ---------------------------------------------------------------------------
// Kernel 0a: split g (fp32, row-major) into bf16 hi/lo tiled+swizzled.
// ---------------------------------------------------------------------------
__global__ __launch_bounds__(256, 4)
void split_g_kernel(const float* __restrict__ g) {
    const int kc = blockIdx.x;
    const int bm = blockIdx.y;
    const int tid = threadIdx.x;
    const size_t tbase = (size_t)(bm * 128 + kc) * 8192;
#pragma unroll
    for (int j = 0; j < 2; j++) {
        const int id  = tid + j * 256;
        const int row = id >> 2;
        const int c16 = id & 3;
        const float* p = g + (size_t)(bm * 128 + row) * KDIM + kc * 32 + c16 * 8;
        const float4 v0 = *(const float4*)p;
        const float4 v1 = *(const float4*)(p + 4);
        uint4 h, l;
        pack8(v0, v1, h, l);
        const uint32_t off = swz64((uint32_t)(row * 64 + c16 * 16));
        *(uint4*)((char*)g_hi_t + tbase + off) = h;
        *(uint4*)((char*)g_lo_t + tbase + off) = l;
    }
}

// ---------------------------------------------------------------------------
// Kernel 0b: weights [K=4096, T=512] -> (w^2)^T tiled bf16 hi/lo.
// ---------------------------------------------------------------------------
__global__ __launch_bounds__(256, 2)
void split_w_kernel(const float* __restrict__ w) {
    __shared__ float tile[128][33];
    const int kc = blockIdx.x;
    const int bn = blockIdx.y;
    const int tid = threadIdx.x;

#pragma unroll
    for (int j = 0; j < 16; j++) {
        const int id = tid + j * 256;
        const int kl = id >> 7;
        const int tl = id & 127;
        const float v = w[(size_t)(kc * 32 + kl) * NCOLS + bn * 128 + tl];
        tile[tl][kl] = v * v;
    }
    __syncthreads();

    const size_t tbase = (size_t)(bn * 128 + kc) * 8192;
#pragma unroll
    for (int j = 0; j < 2; j++) {
        const int id = tid + j * 256;
        const int r  = id >> 2;
        const int c16 = id & 3;
        float4 u, v;
        u.x = tile[r][c16 * 8 + 0]; u.y = tile[r][c16 * 8 + 1];
        u.z = tile[r][c16 * 8 + 2]; u.w = tile[r][c16 * 8 + 3];
        v.x = tile[r][c16 * 8 + 4]; v.y = tile[r][c16 * 8 + 5];
        v.z = tile[r][c16 * 8 + 6]; v.w = tile[r][c16 * 8 + 7];
        uint4 h, l;
        pack8(u, v, h, l);
        const uint32_t off = swz64((uint32_t)(r * 64 + c16 * 16));
        *(uint4*)((char*)w2t_hi_t + tbase + off) = h;
        *(uint4*)((char*)w2t_lo_t + tbase + off) = l;
    }
}

// ---------------------------------------------------------------------------
// Kernel 1: F = g @ weights^2 (bf16 hi/lo split HMMA, TMA loads), fused
// row-softmax epilogue writing TRANSPOSED g_w.
//   Grid (4, 32). CTA tile 128x128 over K=4096. 512 threads = 16 warps
//   (2M x 8N), warp tile 64x16 -> 4 warps/SMSP to hide HMMA/LDSM latency.
// ---------------------------------------------------------------------------
#define ATILE   8192
#define STAGE_B (4 * ATILE)                // 32 KB
#define NSLOT   4
#define SMEM_T  (NSLOT * STAGE_B)          // 128 KB
#define KSTAGES (KDIM / 32)                // 128

__global__ __launch_bounds__(512, 1)
void mma_gemm_kernel(float* __restrict__ F) {
    extern __shared__ char smem[];
    __shared__ uint64_t mbars[NSLOT];
    const uint32_t sb = smem_u32(smem);
    const uint32_t mb0 = smem_u32(&mbars[0]);
    const int tid  = threadIdx.x;
    const int lane = tid & 31;
    const int wid  = tid >> 5;
    const int bn = blockIdx.x;             // 0..3
    const int bm = blockIdx.y;             // 0..31
    const int wm = wid >> 3;               // 0..1 -> row offset wm*64
    const int wn = wid & 7;                // 0..7 -> col offset wn*16

    const char* Ah = (const char*)g_hi_t   + (size_t)(bm * 128) * 8192;
    const char* Al = (const char*)g_lo_t   + (size_t)(bm * 128) * 8192;
    const char* Bh = (const char*)w2t_hi_t + (size_t)(bn * 128) * 8192;
    const char* Bl = (const char*)w2t_lo_t + (size_t)(bn * 128) * 8192;

    if (tid == 0) {
#pragma unroll
        for (int i = 0; i < NSLOT; i++) mbar_init(mb0 + i * 8, 1);
    }
    __syncthreads();

    auto issue = [&](int s) {
        const int slot = s & (NSLOT - 1);
        const uint32_t mb  = mb0 + slot * 8;
        const uint32_t dst = sb + slot * STAGE_B;
        mbar_expect_tx(mb, STAGE_B);
        const size_t to = (size_t)s * 8192;
        cp_bulk8k(dst,             Ah + to, mb);
        cp_bulk8k(dst + ATILE,     Al + to, mb);
        cp_bulk8k(dst + 2 * ATILE, Bh + to, mb);
        cp_bulk8k(dst + 3 * ATILE, Bl + to, mb);
    };

    if (tid == 0) { issue(0); issue(1); issue(2); }

    float c[4][2][4];
#pragma unroll
    for (int mt = 0; mt < 4; mt++)
#pragma unroll
        for (int nt = 0; nt < 2; nt++)
#pragma unroll
            for (int q = 0; q < 4; q++) c[mt][nt][q] = 0.f;

    const int rA    = lane & 15;
    const int kHalf = (lane >> 4) << 4;

    for (int s = 0; s < KSTAGES; s++) {
        const int slot = s & (NSLOT - 1);
        if (tid == 0 && s + 3 < KSTAGES) issue(s + 3);

        mbar_wait(mb0 + slot * 8, (s >> 2) & 1);

        const uint32_t ab = sb + slot * STAGE_B;
        const uint32_t al = ab + ATILE;
        const uint32_t bh = ab + 2 * ATILE;
        const uint32_t bl = ab + 3 * ATILE;

#pragma unroll
        for (int kk = 0; kk < 2; kk++) {
            const int kb = kk * 32 + kHalf;
            uint32_t ahr[4][4], alr[4][4];
#pragma unroll
            for (int mt = 0; mt < 4; mt++) {
                const int row = wm * 64 + mt * 16 + rA;
                const uint32_t off = swz64((uint32_t)(row * 64 + kb));
                LDSM4(ahr[mt], ab + off);
                LDSM4(alr[mt], al + off);
            }
            uint32_t bhr[4], blr[4];
            {
                const int row = wn * 16 + rA;
                const uint32_t off = swz64((uint32_t)(row * 64 + kb));
                LDSM4(bhr, bh + off);
                LDSM4(blr, bl + off);
            }
            // hh pass, then hl, then lh: same-accumulator distance = 8
#pragma unroll
            for (int mt = 0; mt < 4; mt++)
#pragma unroll
                for (int h = 0; h < 2; h++)
                    MMA16816(c[mt][h], ahr[mt], bhr[h], bhr[h + 2]);
#pragma unroll
            for (int mt = 0; mt < 4; mt++)
#pragma unroll
                for (int h = 0; h < 2; h++)
                    MMA16816(c[mt][h], ahr[mt], blr[h], blr[h + 2]);
#pragma unroll
            for (int mt = 0; mt < 4; mt++)
#pragma unroll
                for (int h = 0; h < 2; h++)
                    MMA16816(c[mt][h], alr[mt], bhr[h], bhr[h + 2]);
        }
        __syncthreads();
    }

    // ---- epilogue 1: write raw F (row-major [4096, 512]) ----
    const int r_lo = lane >> 2;
    const int c_lo = (lane & 3) * 2;
#pragma unroll
    for (int mt = 0; mt < 4; mt++) {
        const int row0 = bm * 128 + wm * 64 + mt * 16 + r_lo;
#pragma unroll
        for (int nt = 0; nt < 2; nt++) {
            const int col = bn * 128 + wn * 16 + nt * 8 + c_lo;
            float2 v0 = make_float2(c[mt][nt][0], c[mt][nt][1]);
            float2 v1 = make_float2(c[mt][nt][2], c[mt][nt][3]);
            *(float2*)(F + (size_t)row0 * NCOLS + col)       = v0;
            *(float2*)(F + (size_t)(row0 + 8) * NCOLS + col) = v1;
        }
    }

    // ---- epilogue 2: fused softmax over the warp's 64 rows, per column ----
    // shfl_xor strides 4/8/16 reduce over r_lo while preserving lane&3.
    float mA[2], mB[2], sA[2], sB[2];
#pragma unroll
    for (int nt = 0; nt < 2; nt++) {
        float ma = -3.402823466e+38f, mb = ma;
#pragma unroll
        for (int mt = 0; mt < 4; mt++) {
            ma = fmaxf(ma, fmaxf(c[mt][nt][0], c[mt][nt][2]));
            mb = fmaxf(mb, fmaxf(c[mt][nt][1], c[mt][nt][3]));
        }
        ma = fmaxf(ma, __shfl_xor_sync(0xffffffffu, ma, 4));
        ma = fmaxf(ma, __shfl_xor_sync(0xffffffffu, ma, 8));
        ma = fmaxf(ma, __shfl_xor_sync(0xffffffffu, ma, 16));
        mb = fmaxf(mb, __shfl_xor_sync(0xffffffffu, mb, 4));
        mb = fmaxf(mb, __shfl_xor_sync(0xffffffffu, mb, 8));
        mb = fmaxf(mb, __shfl_xor_sync(0xffffffffu, mb, 16));
        mA[nt] = ma; mB[nt] = mb;
    }
#pragma unroll
    for (int nt = 0; nt < 2; nt++) {
        float sa = 0.f, sbv = 0.f;
#pragma unroll
        for (int mt = 0; mt < 4; mt++) {
            c[mt][nt][0] = __expf(c[mt][nt][0] - mA[nt]);
            c[mt][nt][2] = __expf(c[mt][nt][2] - mA[nt]);
            c[mt][nt][1] = __expf(c[mt][nt][1] - mB[nt]);
            c[mt][nt][3] = __expf(c[mt][nt][3] - mB[nt]);
            sa  += c[mt][nt][0] + c[mt][nt][2];
            sbv += c[mt][nt][1] + c[mt][nt][3];
        }
        sa  += __shfl_xor_sync(0xffffffffu, sa, 4);
        sa  += __shfl_xor_sync(0xffffffffu, sa, 8);
        sa  += __shfl_xor_sync(0xffffffffu, sa, 16);
        sbv += __shfl_xor_sync(0xffffffffu, sbv, 4);
        sbv += __shfl_xor_sync(0xffffffffu, sbv, 8);
        sbv += __shfl_xor_sync(0xffffffffu, sbv, 16);
        sA[nt] = 1.f / sa; sB[nt] = 1.f / sbv;
    }
    // write TRANSPOSED w: g_w[t*4096 + j*64 + i], i = 2*bm + wm (per warp)
    const int iidx = 2 * bm + wm;
#pragma unroll
    for (int nt = 0; nt < 2; nt++) {
        const int colA = bn * 128 + wn * 16 + nt * 8 + c_lo;
#pragma unroll
        for (int mt = 0; mt < 4; mt++) {
            const int j0 = mt * 16 + r_lo;
            g_w[(size_t)colA * KDIM + j0 * 64 + iidx]           = c[mt][nt][0] * sA[nt];
            g_w[(size_t)colA * KDIM + (j0 + 8) * 64 + iidx]     = c[mt][nt][2] * sA[nt];
            g_w[(size_t)(colA + 1) * KDIM + j0 * 64 + iidx]     = c[mt][nt][1] * sB[nt];
            g_w[(size_t)(colA + 1) * KDIM + (j0 + 8) * 64 + iidx] = c[mt][nt][3] * sB[nt];
        }
    }
}

// ---------------------------------------------------------------------------
// Kernel 3: gather partials, coalesced against transposed g_w.
// Grid (B, 4): block z handles p = z*8 .. z*8+7; thread (s = tid/64, n = tid%64)
// handles 2 p's. Warp lanes have consecutive n -> each m-load is one 128B line.
// ---------------------------------------------------------------------------
__global__ __launch_bounds__(256, 4)
void gather_kernel(const float* __restrict__ x,
                   const int* __restrict__ xi) {
    __shared__ float xs[NN * PP];     // xs[m*32 + p]
    __shared__ int   ti[8];
    __shared__ float part[4][NN];

    const int b   = blockIdx.x;
    const int z   = blockIdx.y;
    const int tid = threadIdx.x;

#pragma unroll
    for (int r = 0; r < 8; r++) {
        const int idx = tid + r * 256;
        xs[idx] = x[(size_t)b * (NN * PP) + idx];
    }
    if (tid < 8) ti[tid] = xi[b * PP + z * 8 + tid];
    __syncthreads();

    const int n = tid & 63;
    const int s = tid >> 6;
    float acc = 0.f;
#pragma unroll
    for (int pp = 0; pp < 2; pp++) {
        const int pl = s * 2 + pp;
        const int p  = z * 8 + pl;
        const int t  = ti[pl];
        const float* wrow = g_w + (size_t)t * KDIM + n;   // + m*64 per step
#pragma unroll
        for (int m = 0; m < 64; m += 4) {
            // coalesced: lanes read consecutive n within one 128B line
            acc += wrow[(m + 0) * 64] * xs[(m + 0) * 32 + p];
            acc += wrow[(m + 1) * 64] * xs[(m + 1) * 32 + p];
            acc += wrow[(m + 2) * 64] * xs[(m + 2) * 32 + p];
            acc += wrow[(m + 3) * 64] * xs[(m + 3) * 32 + p];
        }
    }
    part[s][n] = acc;
    __syncthreads();
    if (tid < NN) {
        g_Zp[z][b * NN + tid] =
            part[0][tid] + part[1][tid] + part[2][tid] + part[3][tid];
    }
}

__global__ __launch_bounds__(256, 4)
void zfinal_kernel(float* __restrict__ Z) {
    const int i = blockIdx.x * 256 + threadIdx.x;
    Z[i] = g_Zp[0][i] + g_Zp[1][i] + g_Zp[2][i] + g_Zp[3][i];
}

// ---------------------------------------------------------------------------
// Launch. Inputs: x [B,N,P] f32, x_i [B,P] i32, g [4096,4096] f32,
//                 weights [4096,512] f32.  Output: Z (4096 f32) then F.
// ---------------------------------------------------------------------------
extern "C" void kernel_launch(void* const* d_in, const int* in_sizes, int n_in,
                              void* d_out, int out_size) {
    const float* x   = (const float*)d_in[0];
    const int*   xi  = (const int*)d_in[1];
    const float* g   = (const float*)d_in[2];
    const float* wts = (const float*)d_in[3];

    float* Z = (float*)d_out;
    float* F = (float*)d_out + NN * NN;

    cudaFuncSetAttribute(mma_gemm_kernel,
                         cudaFuncAttributeMaxDynamicSharedMemorySize, SMEM_T);

    split_g_kernel<<<dim3(KDIM / 32, KDIM / 128), 256>>>(g);
    split_w_kernel<<<dim3(KDIM / 32, NCOLS / 128), 256>>>(wts);

    mma_gemm_kernel<<<dim3(NCOLS / 128, KDIM / 128), 512, SMEM_T>>>(F);

    gather_kernel<<<dim3(BB, 4), 256>>>(x, xi);
    zfinal_kernel<<<(BB * NN) / 256, 256>>>(Z);
}

// round 11
// speedup vs baseline: 1.9614x; 1.9614x over previous
#include <cuda_runtime.h>
#include <cuda_fp16.h>
#include <cstdint>

// Problem constants
#define NN      64
#define TT      512
#define BB      64
#define PP      32
#define KDIM    4096        // N*N
#define NCOLS   512         // T

// ---------------------------------------------------------------------------
// Device scratch (static — allocation-free per harness rules)
// g_w layout: g_w[t*4096 + i*64 + j]   (as in R9-best)
// Operands stored TILED fp16: tile = [128 rows x 32 k] = 8 KB contiguous,
// SW64-swizzled; GEMM fetches a stage with 2 TMA bulk copies.
//   A tiles: tile_id = bm*128 + kc   (bm 0..31, kc 0..127)
//   B tiles: tile_id = bn*128 + kc   (bn 0..3,  kc 0..127)
// ---------------------------------------------------------------------------
__device__ float g_w[TT * KDIM];
__device__ __half g_f16_t[(size_t)KDIM * KDIM];        // 33.5 MB tiled
__device__ __half w2t_f16_t[(size_t)NCOLS * KDIM];     // 4 MB tiled
__device__ float g_Zp[4][BB * NN];                     // gather partials

// ---------------------------------------------------------------------------
// PTX helpers (baseline sm_90-level PTX, valid on plain sm_103 target)
// ---------------------------------------------------------------------------
__device__ __forceinline__ uint32_t smem_u32(const void* p) {
    uint32_t a;
    asm("{ .reg .u64 t; cvta.to.shared.u64 t, %1; cvt.u32.u64 %0, t; }"
        : "=r"(a) : "l"(p));
    return a;
}

__device__ __forceinline__ void cp_bulk8k(uint32_t dst, const void* src,
                                          uint32_t mbar) {
    asm volatile(
        "cp.async.bulk.shared::cluster.global.mbarrier::complete_tx::bytes "
        "[%0], [%1], %2, [%3];"
        :: "r"(dst), "l"(src), "r"(8192u), "r"(mbar) : "memory");
}

__device__ __forceinline__ void mbar_init(uint32_t mbar, uint32_t cnt) {
    asm volatile("mbarrier.init.shared.b64 [%0], %1;" :: "r"(mbar), "r"(cnt)
                 : "memory");
}

__device__ __forceinline__ void mbar_expect_tx(uint32_t mbar, uint32_t bytes) {
    asm volatile("mbarrier.arrive.expect_tx.shared.b64 _, [%0], %1;"
                 :: "r"(mbar), "r"(bytes) : "memory");
}

__device__ __forceinline__ void mbar_wait(uint32_t mbar, uint32_t parity) {
    asm volatile(
        "{\n\t"
        ".reg .pred P1;\n\t"
        "WAIT_LOOP_%=:\n\t"
        "mbarrier.try_wait.parity.acquire.cta.shared::cta.b64 P1, [%0], %1, 0x989680;\n\t"
        "@P1 bra.uni WAIT_DONE_%=;\n\t"
        "bra.uni WAIT_LOOP_%=;\n\t"
        "WAIT_DONE_%=:\n\t"
        "}"
        :: "r"(mbar), "r"(parity) : "memory");
}

#define LDSM4(r, addr)                                                         \
    asm volatile("ldmatrix.sync.aligned.m8n8.x4.shared.b16 "                   \
                 "{%0,%1,%2,%3}, [%4];"                                        \
                 : "=r"((r)[0]), "=r"((r)[1]), "=r"((r)[2]), "=r"((r)[3])      \
                 : "r"(addr))

#define MMA16816F16(c, a, b0, b1)                                              \
    asm volatile("mma.sync.aligned.m16n8k16.row.col.f32.f16.f16.f32 "          \
                 "{%0,%1,%2,%3},{%4,%5,%6,%7},{%8,%9},{%0,%1,%2,%3};"          \
                 : "+f"((c)[0]), "+f"((c)[1]), "+f"((c)[2]), "+f"((c)[3])      \
                 : "r"((a)[0]), "r"((a)[1]), "r"((a)[2]), "r"((a)[3]),         \
                   "r"(b0), "r"(b1))

// SW64 swizzle for 64-byte rows (conflict-free ldmatrix, proven)
__device__ __forceinline__ uint32_t swz64(uint32_t off) {
    return off ^ ((off >> 3) & 0x30);
}

__device__ __forceinline__ uint32_t pk_h2(float x, float y) {
    return ((uint32_t)__half_as_ushort(__float2half_rn(y)) << 16) |
           __half_as_ushort(__float2half_rn(x));
}
__device__ __forceinline__ uint4 pack8_f16(const float4& u, const float4& v) {
    uint4 h;
    h.x = pk_h2(u.x, u.y); h.y = pk_h2(u.z, u.w);
    h.z = pk_h2(v.x, v.y); h.w = pk_h2(v.z, v.w);
    return h;
}

// ---------------------------------------------------------------------------
// Kernel 0a: convert g (fp32, row-major) to fp16 tiled+swizzled.
// Grid (kc=128, bm=32); one block writes one 8KB tile, fully coalesced.
// ---------------------------------------------------------------------------
__global__ __launch_bounds__(256, 4)
void split_g_kernel(const float* __restrict__ g) {
    const int kc = blockIdx.x;
    const int bm = blockIdx.y;
    const int tid = threadIdx.x;
    const size_t tbase = (size_t)(bm * 128 + kc) * 8192;
#pragma unroll
    for (int j = 0; j < 2; j++) {
        const int id  = tid + j * 256;
        const int row = id >> 2;
        const int c16 = id & 3;
        const float* p = g + (size_t)(bm * 128 + row) * KDIM + kc * 32 + c16 * 8;
        const float4 v0 = *(const float4*)p;
        const float4 v1 = *(const float4*)(p + 4);
        const uint4 h = pack8_f16(v0, v1);
        const uint32_t off = swz64((uint32_t)(row * 64 + c16 * 16));
        *(uint4*)((char*)g_f16_t + tbase + off) = h;
    }
}

// ---------------------------------------------------------------------------
// Kernel 0b: weights [K=4096, T=512] -> (w^2)^T tiled fp16.
// ---------------------------------------------------------------------------
__global__ __launch_bounds__(256, 2)
void split_w_kernel(const float* __restrict__ w) {
    __shared__ float tile[128][33];   // [t_local][k_local]
    const int kc = blockIdx.x;
    const int bn = blockIdx.y;
    const int tid = threadIdx.x;

#pragma unroll
    for (int j = 0; j < 16; j++) {
        const int id = tid + j * 256;
        const int kl = id >> 7;
        const int tl = id & 127;
        const float v = w[(size_t)(kc * 32 + kl) * NCOLS + bn * 128 + tl];
        tile[tl][kl] = v * v;
    }
    __syncthreads();

    const size_t tbase = (size_t)(bn * 128 + kc) * 8192;
#pragma unroll
    for (int j = 0; j < 2; j++) {
        const int id = tid + j * 256;
        const int r  = id >> 2;
        const int c16 = id & 3;
        float4 u, v;
        u.x = tile[r][c16 * 8 + 0]; u.y = tile[r][c16 * 8 + 1];
        u.z = tile[r][c16 * 8 + 2]; u.w = tile[r][c16 * 8 + 3];
        v.x = tile[r][c16 * 8 + 4]; v.y = tile[r][c16 * 8 + 5];
        v.z = tile[r][c16 * 8 + 6]; v.w = tile[r][c16 * 8 + 7];
        const uint4 h = pack8_f16(u, v);
        const uint32_t off = swz64((uint32_t)(r * 64 + c16 * 16));
        *(uint4*)((char*)w2t_f16_t + tbase + off) = h;
    }
}

// ---------------------------------------------------------------------------
// Kernel 1: F = g @ weights^2, single-pass fp16 HMMA, TMA loads, fused
// row-softmax epilogue (R9 structure).
//   Grid (4, 32). CTA tile 128x128 over K=4096. 256 threads = 8 warps
//   (2M x 4N), warp tile 64x32. 128 stages of K=32; stage = 2 x 8KB bulk
//   copies (A, B). 8-slot mbarrier ring, 128 KB smem, grid 128 = one wave.
// ---------------------------------------------------------------------------
#define ATILE   8192
#define STAGE_B (2 * ATILE)                // 16 KB
#define NSLOT   8
#define SMEM_T  (NSLOT * STAGE_B)          // 128 KB
#define KSTAGES (KDIM / 32)                // 128

__global__ __launch_bounds__(256, 1)
void mma_gemm_kernel(float* __restrict__ F) {
    extern __shared__ char smem[];
    __shared__ uint64_t mbars[NSLOT];
    const uint32_t sb = smem_u32(smem);
    const uint32_t mb0 = smem_u32(&mbars[0]);
    const int tid  = threadIdx.x;
    const int lane = tid & 31;
    const int wid  = tid >> 5;
    const int bn = blockIdx.x;             // 0..3
    const int bm = blockIdx.y;             // 0..31
    const int wm = wid >> 2;               // 0..1 -> row offset wm*64
    const int wn = wid & 3;                // 0..3 -> col offset wn*32

    const char* Ag = (const char*)g_f16_t   + (size_t)(bm * 128) * 8192;
    const char* Bg = (const char*)w2t_f16_t + (size_t)(bn * 128) * 8192;

    if (tid == 0) {
#pragma unroll
        for (int i = 0; i < NSLOT; i++) mbar_init(mb0 + i * 8, 1);
    }
    __syncthreads();

    auto issue = [&](int s) {
        const int slot = s & (NSLOT - 1);
        const uint32_t mb  = mb0 + slot * 8;
        const uint32_t dst = sb + slot * STAGE_B;
        mbar_expect_tx(mb, STAGE_B);
        const size_t to = (size_t)s * 8192;
        cp_bulk8k(dst,         Ag + to, mb);
        cp_bulk8k(dst + ATILE, Bg + to, mb);
    };

    if (tid == 0) {
#pragma unroll
        for (int i = 0; i < NSLOT - 1; i++) issue(i);
    }

    float c[4][4][4];
#pragma unroll
    for (int mt = 0; mt < 4; mt++)
#pragma unroll
        for (int nt = 0; nt < 4; nt++)
#pragma unroll
            for (int q = 0; q < 4; q++) c[mt][nt][q] = 0.f;

    const int rA    = lane & 15;
    const int kHalf = (lane >> 4) << 4;

    for (int s = 0; s < KSTAGES; s++) {
        const int slot = s & (NSLOT - 1);
        if (tid == 0 && s + NSLOT - 1 < KSTAGES) issue(s + NSLOT - 1);

        mbar_wait(mb0 + slot * 8, (s >> 3) & 1);

        const uint32_t ab = sb + slot * STAGE_B;
        const uint32_t bb = ab + ATILE;

#pragma unroll
        for (int kk = 0; kk < 2; kk++) {
            const int kb = kk * 32 + kHalf;
            uint32_t ahr[4][4];
#pragma unroll
            for (int mt = 0; mt < 4; mt++) {
                const int row = wm * 64 + mt * 16 + rA;
                const uint32_t off = swz64((uint32_t)(row * 64 + kb));
                LDSM4(ahr[mt], ab + off);
            }
#pragma unroll
            for (int gg = 0; gg < 2; gg++) {
                uint32_t bhr[4];
                const int row = wn * 32 + gg * 16 + rA;
                const uint32_t off = swz64((uint32_t)(row * 64 + kb));
                LDSM4(bhr, bb + off);
#pragma unroll
                for (int mt = 0; mt < 4; mt++)
#pragma unroll
                    for (int h = 0; h < 2; h++)
                        MMA16816F16(c[mt][gg * 2 + h], ahr[mt], bhr[h], bhr[h + 2]);
            }
        }
        __syncthreads();     // all warps done reading slot before reuse
    }

    // ---- epilogue 1: write raw F (row-major [4096, 512]) ----
    const int r_lo = lane >> 2;
    const int c_lo = (lane & 3) * 2;
#pragma unroll
    for (int mt = 0; mt < 4; mt++) {
        const int row0 = bm * 128 + wm * 64 + mt * 16 + r_lo;
#pragma unroll
        for (int nt = 0; nt < 4; nt++) {
            const int col = bn * 128 + wn * 32 + nt * 8 + c_lo;
            float2 v0 = make_float2(c[mt][nt][0], c[mt][nt][1]);
            float2 v1 = make_float2(c[mt][nt][2], c[mt][nt][3]);
            *(float2*)(F + (size_t)row0 * NCOLS + col)       = v0;
            *(float2*)(F + (size_t)(row0 + 8) * NCOLS + col) = v1;
        }
    }

    // ---- epilogue 2: fused softmax over the warp's 64 rows, per column ----
    float mA[4], mB[4], sA[4], sB[4];
#pragma unroll
    for (int nt = 0; nt < 4; nt++) {
        float ma = -3.402823466e+38f, mb = ma;
#pragma unroll
        for (int mt = 0; mt < 4; mt++) {
            ma = fmaxf(ma, fmaxf(c[mt][nt][0], c[mt][nt][2]));
            mb = fmaxf(mb, fmaxf(c[mt][nt][1], c[mt][nt][3]));
        }
        ma = fmaxf(ma, __shfl_xor_sync(0xffffffffu, ma, 4));
        ma = fmaxf(ma, __shfl_xor_sync(0xffffffffu, ma, 8));
        ma = fmaxf(ma, __shfl_xor_sync(0xffffffffu, ma, 16));
        mb = fmaxf(mb, __shfl_xor_sync(0xffffffffu, mb, 4));
        mb = fmaxf(mb, __shfl_xor_sync(0xffffffffu, mb, 8));
        mb = fmaxf(mb, __shfl_xor_sync(0xffffffffu, mb, 16));
        mA[nt] = ma; mB[nt] = mb;
    }
#pragma unroll
    for (int nt = 0; nt < 4; nt++) {
        float sa = 0.f, sbv = 0.f;
#pragma unroll
        for (int mt = 0; mt < 4; mt++) {
            c[mt][nt][0] = __expf(c[mt][nt][0] - mA[nt]);
            c[mt][nt][2] = __expf(c[mt][nt][2] - mA[nt]);
            c[mt][nt][1] = __expf(c[mt][nt][1] - mB[nt]);
            c[mt][nt][3] = __expf(c[mt][nt][3] - mB[nt]);
            sa  += c[mt][nt][0] + c[mt][nt][2];
            sbv += c[mt][nt][1] + c[mt][nt][3];
        }
        sa  += __shfl_xor_sync(0xffffffffu, sa, 4);
        sa  += __shfl_xor_sync(0xffffffffu, sa, 8);
        sa  += __shfl_xor_sync(0xffffffffu, sa, 16);
        sbv += __shfl_xor_sync(0xffffffffu, sbv, 4);
        sbv += __shfl_xor_sync(0xffffffffu, sbv, 8);
        sbv += __shfl_xor_sync(0xffffffffu, sbv, 16);
        sA[nt] = 1.f / sa; sB[nt] = 1.f / sbv;
    }
    // write w: g_w[t*4096 + i*64 + j], i = 2*bm + wm (one i-group per warp)
    const int ibase = (2 * bm + wm) * 64;
#pragma unroll
    for (int nt = 0; nt < 4; nt++) {
        const int colA = bn * 128 + wn * 32 + nt * 8 + c_lo;
#pragma unroll
        for (int mt = 0; mt < 4; mt++) {
            const int j0 = mt * 16 + r_lo;
            g_w[(size_t)colA * KDIM + ibase + j0]           = c[mt][nt][0] * sA[nt];
            g_w[(size_t)colA * KDIM + ibase + j0 + 8]       = c[mt][nt][2] * sA[nt];
            g_w[(size_t)(colA + 1) * KDIM + ibase + j0]     = c[mt][nt][1] * sB[nt];
            g_w[(size_t)(colA + 1) * KDIM + ibase + j0 + 8] = c[mt][nt][3] * sB[nt];
        }
    }
}

// ---------------------------------------------------------------------------
// Kernel 3: gather partials. Grid (B, 4): block z handles p = z*8 .. z*8+7.
// (R9-best version: g_w rows [t][n*64 + m], float4 reads.)
// ---------------------------------------------------------------------------
__global__ __launch_bounds__(256, 4)
void gather_kernel(const float* __restrict__ x,
                   const int* __restrict__ xi) {
    __shared__ float xs[NN * PP];     // xs[m*32 + p]
    __shared__ int   ti[8];
    __shared__ float part[4][NN];

    const int b   = blockIdx.x;
    const int z   = blockIdx.y;
    const int tid = threadIdx.x;

#pragma unroll
    for (int r = 0; r < 8; r++) {
        const int idx = tid + r * 256;
        xs[idx] = x[(size_t)b * (NN * PP) + idx];
    }
    if (tid < 8) ti[tid] = xi[b * PP + z * 8 + tid];
    __syncthreads();

    const int n = tid & 63;
    const int s = tid >> 6;
    float acc = 0.f;
#pragma unroll
    for (int pp = 0; pp < 2; pp++) {
        const int pl = s * 2 + pp;
        const int p  = z * 8 + pl;
        const int t  = ti[pl];
        const float4* row = (const float4*)(g_w + (size_t)t * KDIM + n * 64);
#pragma unroll
        for (int q = 0; q < 16; q++) {
            const float4 v = row[q];
            const int m = q * 4;
            acc += v.x * xs[(m + 0) * 32 + p];
            acc += v.y * xs[(m + 1) * 32 + p];
            acc += v.z * xs[(m + 2) * 32 + p];
            acc += v.w * xs[(m + 3) * 32 + p];
        }
    }
    part[s][n] = acc;
    __syncthreads();
    if (tid < NN) {
        g_Zp[z][b * NN + tid] =
            part[0][tid] + part[1][tid] + part[2][tid] + part[3][tid];
    }
}

__global__ __launch_bounds__(256, 4)
void zfinal_kernel(float* __restrict__ Z) {
    const int i = blockIdx.x * 256 + threadIdx.x;
    Z[i] = g_Zp[0][i] + g_Zp[1][i] + g_Zp[2][i] + g_Zp[3][i];
}

// ---------------------------------------------------------------------------
// Launch. Inputs: x [B,N,P] f32, x_i [B,P] i32, g [4096,4096] f32,
//                 weights [4096,512] f32.  Output: Z (4096 f32) then F.
// ---------------------------------------------------------------------------
extern "C" void kernel_launch(void* const* d_in, const int* in_sizes, int n_in,
                              void* d_out, int out_size) {
    const float* x   = (const float*)d_in[0];
    const int*   xi  = (const int*)d_in[1];
    const float* g   = (const float*)d_in[2];
    const float* wts = (const float*)d_in[3];

    float* Z = (float*)d_out;
    float* F = (float*)d_out + NN * NN;

    cudaFuncSetAttribute(mma_gemm_kernel,
                         cudaFuncAttributeMaxDynamicSharedMemorySize, SMEM_T);

    split_g_kernel<<<dim3(KDIM / 32, KDIM / 128), 256>>>(g);
    split_w_kernel<<<dim3(KDIM / 32, NCOLS / 128), 256>>>(wts);

    mma_gemm_kernel<<<dim3(NCOLS / 128, KDIM / 128), 256, SMEM_T>>>(F);

    gather_kernel<<<dim3(BB, 4), 256>>>(x, xi);
    zfinal_kernel<<<(BB * NN) / 256, 256>>>(Z);
}

// round 12
// speedup vs baseline: 2.0003x; 1.0198x over previous
#include <cuda_runtime.h>
#include <cuda_fp16.h>
#include <cstdint>

// Problem constants
#define NN      64
#define TT      512
#define BB      64
#define PP      32
#define KDIM    4096        // N*N
#define NCOLS   512         // T

// ---------------------------------------------------------------------------
// Device scratch (static — allocation-free per harness rules)
// g_w layout: g_w[t*4096 + i*64 + j]
// Operands stored TILED fp16: tile = [128 rows x 32 k] = 8 KB contiguous,
// SW64-swizzled; GEMM fetches a stage with 2 TMA bulk copies.
// ---------------------------------------------------------------------------
__device__ float g_w[TT * KDIM];
__device__ __half g_f16_t[(size_t)KDIM * KDIM];        // 33.5 MB tiled
__device__ __half w2t_f16_t[(size_t)NCOLS * KDIM];     // 4 MB tiled
__device__ float g_Zp[PP][BB * NN];                    // per-p gather partials

// ---------------------------------------------------------------------------
// PTX helpers (baseline sm_90-level PTX, valid on plain sm_103 target)
// ---------------------------------------------------------------------------
__device__ __forceinline__ uint32_t smem_u32(const void* p) {
    uint32_t a;
    asm("{ .reg .u64 t; cvta.to.shared.u64 t, %1; cvt.u32.u64 %0, t; }"
        : "=r"(a) : "l"(p));
    return a;
}

__device__ __forceinline__ void cp_bulk8k(uint32_t dst, const void* src,
                                          uint32_t mbar) {
    asm volatile(
        "cp.async.bulk.shared::cluster.global.mbarrier::complete_tx::bytes "
        "[%0], [%1], %2, [%3];"
        :: "r"(dst), "l"(src), "r"(8192u), "r"(mbar) : "memory");
}

__device__ __forceinline__ void mbar_init(uint32_t mbar, uint32_t cnt) {
    asm volatile("mbarrier.init.shared.b64 [%0], %1;" :: "r"(mbar), "r"(cnt)
                 : "memory");
}

__device__ __forceinline__ void mbar_expect_tx(uint32_t mbar, uint32_t bytes) {
    asm volatile("mbarrier.arrive.expect_tx.shared.b64 _, [%0], %1;"
                 :: "r"(mbar), "r"(bytes) : "memory");
}

__device__ __forceinline__ void mbar_wait(uint32_t mbar, uint32_t parity) {
    asm volatile(
        "{\n\t"
        ".reg .pred P1;\n\t"
        "WAIT_LOOP_%=:\n\t"
        "mbarrier.try_wait.parity.acquire.cta.shared::cta.b64 P1, [%0], %1, 0x989680;\n\t"
        "@P1 bra.uni WAIT_DONE_%=;\n\t"
        "bra.uni WAIT_LOOP_%=;\n\t"
        "WAIT_DONE_%=:\n\t"
        "}"
        :: "r"(mbar), "r"(parity) : "memory");
}

#define LDSM4(r, addr)                                                         \
    asm volatile("ldmatrix.sync.aligned.m8n8.x4.shared.b16 "                   \
                 "{%0,%1,%2,%3}, [%4];"                                        \
                 : "=r"((r)[0]), "=r"((r)[1]), "=r"((r)[2]), "=r"((r)[3])      \
                 : "r"(addr))

#define MMA16816F16(c, a, b0, b1)                                              \
    asm volatile("mma.sync.aligned.m16n8k16.row.col.f32.f16.f16.f32 "          \
                 "{%0,%1,%2,%3},{%4,%5,%6,%7},{%8,%9},{%0,%1,%2,%3};"          \
                 : "+f"((c)[0]), "+f"((c)[1]), "+f"((c)[2]), "+f"((c)[3])      \
                 : "r"((a)[0]), "r"((a)[1]), "r"((a)[2]), "r"((a)[3]),         \
                   "r"(b0), "r"(b1))

// SW64 swizzle for 64-byte rows (conflict-free ldmatrix, proven)
__device__ __forceinline__ uint32_t swz64(uint32_t off) {
    return off ^ ((off >> 3) & 0x30);
}

__device__ __forceinline__ uint32_t pk_h2(float x, float y) {
    return ((uint32_t)__half_as_ushort(__float2half_rn(y)) << 16) |
           __half_as_ushort(__float2half_rn(x));
}
__device__ __forceinline__ uint4 pack8_f16(const float4& u, const float4& v) {
    uint4 h;
    h.x = pk_h2(u.x, u.y); h.y = pk_h2(u.z, u.w);
    h.z = pk_h2(v.x, v.y); h.w = pk_h2(v.z, v.w);
    return h;
}

// ---------------------------------------------------------------------------
// Kernel 0a: convert g (fp32, row-major) to fp16 tiled+swizzled.
// ---------------------------------------------------------------------------
__global__ __launch_bounds__(256, 4)
void split_g_kernel(const float* __restrict__ g) {
    const int kc = blockIdx.x;
    const int bm = blockIdx.y;
    const int tid = threadIdx.x;
    const size_t tbase = (size_t)(bm * 128 + kc) * 8192;
#pragma unroll
    for (int j = 0; j < 2; j++) {
        const int id  = tid + j * 256;
        const int row = id >> 2;
        const int c16 = id & 3;
        const float* p = g + (size_t)(bm * 128 + row) * KDIM + kc * 32 + c16 * 8;
        const float4 v0 = *(const float4*)p;
        const float4 v1 = *(const float4*)(p + 4);
        const uint4 h = pack8_f16(v0, v1);
        const uint32_t off = swz64((uint32_t)(row * 64 + c16 * 16));
        *(uint4*)((char*)g_f16_t + tbase + off) = h;
    }
}

// ---------------------------------------------------------------------------
// Kernel 0b: weights [K=4096, T=512] -> (w^2)^T tiled fp16.
// ---------------------------------------------------------------------------
__global__ __launch_bounds__(256, 2)
void split_w_kernel(const float* __restrict__ w) {
    __shared__ float tile[128][33];   // [t_local][k_local]
    const int kc = blockIdx.x;
    const int bn = blockIdx.y;
    const int tid = threadIdx.x;

#pragma unroll
    for (int j = 0; j < 16; j++) {
        const int id = tid + j * 256;
        const int kl = id >> 7;
        const int tl = id & 127;
        const float v = w[(size_t)(kc * 32 + kl) * NCOLS + bn * 128 + tl];
        tile[tl][kl] = v * v;
    }
    __syncthreads();

    const size_t tbase = (size_t)(bn * 128 + kc) * 8192;
#pragma unroll
    for (int j = 0; j < 2; j++) {
        const int id = tid + j * 256;
        const int r  = id >> 2;
        const int c16 = id & 3;
        float4 u, v;
        u.x = tile[r][c16 * 8 + 0]; u.y = tile[r][c16 * 8 + 1];
        u.z = tile[r][c16 * 8 + 2]; u.w = tile[r][c16 * 8 + 3];
        v.x = tile[r][c16 * 8 + 4]; v.y = tile[r][c16 * 8 + 5];
        v.z = tile[r][c16 * 8 + 6]; v.w = tile[r][c16 * 8 + 7];
        const uint4 h = pack8_f16(u, v);
        const uint32_t off = swz64((uint32_t)(r * 64 + c16 * 16));
        *(uint4*)((char*)w2t_f16_t + tbase + off) = h;
    }
}

// ---------------------------------------------------------------------------
// Kernel 1: F = g @ weights^2, single-pass fp16 HMMA, TMA loads, fused
// row-softmax epilogue with smem-staged coalesced g_w stores.
//   Grid (4, 32). CTA tile 128x128 over K=4096. 256 threads = 8 warps
//   (2M x 4N), warp tile 64x32. 8-slot TMA ring, 128 KB smem.
// ---------------------------------------------------------------------------
#define ATILE   8192
#define STAGE_B (2 * ATILE)                // 16 KB
#define NSLOT   8
#define SMEM_T  (NSLOT * STAGE_B)          // 128 KB
#define KSTAGES (KDIM / 32)                // 128

__global__ __launch_bounds__(256, 1)
void mma_gemm_kernel(float* __restrict__ F) {
    extern __shared__ char smem[];
    __shared__ uint64_t mbars[NSLOT];
    const uint32_t sb = smem_u32(smem);
    const uint32_t mb0 = smem_u32(&mbars[0]);
    const int tid  = threadIdx.x;
    const int lane = tid & 31;
    const int wid  = tid >> 5;
    const int bn = blockIdx.x;             // 0..3
    const int bm = blockIdx.y;             // 0..31
    const int wm = wid >> 2;               // 0..1 -> row offset wm*64
    const int wn = wid & 3;                // 0..3 -> col offset wn*32

    const char* Ag = (const char*)g_f16_t   + (size_t)(bm * 128) * 8192;
    const char* Bg = (const char*)w2t_f16_t + (size_t)(bn * 128) * 8192;

    if (tid == 0) {
#pragma unroll
        for (int i = 0; i < NSLOT; i++) mbar_init(mb0 + i * 8, 1);
    }
    __syncthreads();

    auto issue = [&](int s) {
        const int slot = s & (NSLOT - 1);
        const uint32_t mb  = mb0 + slot * 8;
        const uint32_t dst = sb + slot * STAGE_B;
        mbar_expect_tx(mb, STAGE_B);
        const size_t to = (size_t)s * 8192;
        cp_bulk8k(dst,         Ag + to, mb);
        cp_bulk8k(dst + ATILE, Bg + to, mb);
    };

    if (tid == 0) {
#pragma unroll
        for (int i = 0; i < NSLOT - 1; i++) issue(i);
    }

    float c[4][4][4];
#pragma unroll
    for (int mt = 0; mt < 4; mt++)
#pragma unroll
        for (int nt = 0; nt < 4; nt++)
#pragma unroll
            for (int q = 0; q < 4; q++) c[mt][nt][q] = 0.f;

    const int rA    = lane & 15;
    const int kHalf = (lane >> 4) << 4;

    for (int s = 0; s < KSTAGES; s++) {
        const int slot = s & (NSLOT - 1);
        if (tid == 0 && s + NSLOT - 1 < KSTAGES) issue(s + NSLOT - 1);

        mbar_wait(mb0 + slot * 8, (s >> 3) & 1);

        const uint32_t ab = sb + slot * STAGE_B;
        const uint32_t bb = ab + ATILE;

#pragma unroll
        for (int kk = 0; kk < 2; kk++) {
            const int kb = kk * 32 + kHalf;
            uint32_t ahr[4][4];
#pragma unroll
            for (int mt = 0; mt < 4; mt++) {
                const int row = wm * 64 + mt * 16 + rA;
                const uint32_t off = swz64((uint32_t)(row * 64 + kb));
                LDSM4(ahr[mt], ab + off);
            }
#pragma unroll
            for (int gg = 0; gg < 2; gg++) {
                uint32_t bhr[4];
                const int row = wn * 32 + gg * 16 + rA;
                const uint32_t off = swz64((uint32_t)(row * 64 + kb));
                LDSM4(bhr, bb + off);
#pragma unroll
                for (int mt = 0; mt < 4; mt++)
#pragma unroll
                    for (int h = 0; h < 2; h++)
                        MMA16816F16(c[mt][gg * 2 + h], ahr[mt], bhr[h], bhr[h + 2]);
            }
        }
        __syncthreads();     // all warps done reading slot before reuse
    }

    // ---- epilogue 1: write raw F (row-major [4096, 512]) ----
    const int r_lo = lane >> 2;
    const int c_lo = (lane & 3) * 2;
#pragma unroll
    for (int mt = 0; mt < 4; mt++) {
        const int row0 = bm * 128 + wm * 64 + mt * 16 + r_lo;
#pragma unroll
        for (int nt = 0; nt < 4; nt++) {
            const int col = bn * 128 + wn * 32 + nt * 8 + c_lo;
            float2 v0 = make_float2(c[mt][nt][0], c[mt][nt][1]);
            float2 v1 = make_float2(c[mt][nt][2], c[mt][nt][3]);
            *(float2*)(F + (size_t)row0 * NCOLS + col)       = v0;
            *(float2*)(F + (size_t)(row0 + 8) * NCOLS + col) = v1;
        }
    }

    // ---- epilogue 2: fused softmax over the warp's 64 rows, per column ----
    float mA[4], mB[4], sA[4], sB[4];
#pragma unroll
    for (int nt = 0; nt < 4; nt++) {
        float ma = -3.402823466e+38f, mb = ma;
#pragma unroll
        for (int mt = 0; mt < 4; mt++) {
            ma = fmaxf(ma, fmaxf(c[mt][nt][0], c[mt][nt][2]));
            mb = fmaxf(mb, fmaxf(c[mt][nt][1], c[mt][nt][3]));
        }
        ma = fmaxf(ma, __shfl_xor_sync(0xffffffffu, ma, 4));
        ma = fmaxf(ma, __shfl_xor_sync(0xffffffffu, ma, 8));
        ma = fmaxf(ma, __shfl_xor_sync(0xffffffffu, ma, 16));
        mb = fmaxf(mb, __shfl_xor_sync(0xffffffffu, mb, 4));
        mb = fmaxf(mb, __shfl_xor_sync(0xffffffffu, mb, 8));
        mb = fmaxf(mb, __shfl_xor_sync(0xffffffffu, mb, 16));
        mA[nt] = ma; mB[nt] = mb;
    }
#pragma unroll
    for (int nt = 0; nt < 4; nt++) {
        float sa = 0.f, sbv = 0.f;
#pragma unroll
        for (int mt = 0; mt < 4; mt++) {
            c[mt][nt][0] = __expf(c[mt][nt][0] - mA[nt]);
            c[mt][nt][2] = __expf(c[mt][nt][2] - mA[nt]);
            c[mt][nt][1] = __expf(c[mt][nt][1] - mB[nt]);
            c[mt][nt][3] = __expf(c[mt][nt][3] - mB[nt]);
            sa  += c[mt][nt][0] + c[mt][nt][2];
            sbv += c[mt][nt][1] + c[mt][nt][3];
        }
        sa  += __shfl_xor_sync(0xffffffffu, sa, 4);
        sa  += __shfl_xor_sync(0xffffffffu, sa, 8);
        sa  += __shfl_xor_sync(0xffffffffu, sa, 16);
        sbv += __shfl_xor_sync(0xffffffffu, sbv, 4);
        sbv += __shfl_xor_sync(0xffffffffu, sbv, 8);
        sbv += __shfl_xor_sync(0xffffffffu, sbv, 16);
        sA[nt] = 1.f / sa; sB[nt] = 1.f / sbv;
    }

    // ---- epilogue 3: stage w through (now idle) pipeline smem, then store
    //      coalesced. Warp layout sw[tl*72 + j], tl = local t (0..31),
    //      j = 0..63; stride 72 keeps bank conflicts <= 2-way.
    float* sw = (float*)smem + wid * 2304;   // 2304 floats = 9216 B per warp
#pragma unroll
    for (int nt = 0; nt < 4; nt++) {
        const int tl = nt * 8 + c_lo;         // even 0..30
#pragma unroll
        for (int mt = 0; mt < 4; mt++) {
            const int j0 = mt * 16 + r_lo;
            sw[tl * 72 + j0]           = c[mt][nt][0] * sA[nt];
            sw[tl * 72 + j0 + 8]       = c[mt][nt][2] * sA[nt];
            sw[(tl + 1) * 72 + j0]     = c[mt][nt][1] * sB[nt];
            sw[(tl + 1) * 72 + j0 + 8] = c[mt][nt][3] * sB[nt];
        }
    }
    __syncwarp();
    // w: g_w[t*4096 + i*64 + j], i = 2*bm + wm (one i-group per warp)
    const int ibase = (2 * bm + wm) * 64;
    const int tbase = bn * 128 + wn * 32;
#pragma unroll
    for (int tl = 0; tl < 32; tl++) {
        const float v0 = sw[tl * 72 + lane];
        const float v1 = sw[tl * 72 + 32 + lane];
        float* dst = g_w + (size_t)(tbase + tl) * KDIM + ibase;
        dst[lane]      = v0;
        dst[32 + lane] = v1;
    }
}

// ---------------------------------------------------------------------------
// Kernel 3: gather. Grid (B, P) = (64, 32) blocks, 128 threads.
// Block (b,p): out[n] = sum_m g_w[t*4096 + n*64 + m] * x[b, m, p].
// Warp lanes cover m (float2, 256B coalesced); shfl butterfly reduces;
// warp wid handles n = wid*16 .. wid*16+15. Partials to g_Zp[p].
// ---------------------------------------------------------------------------
__global__ __launch_bounds__(128, 8)
void gather_kernel(const float* __restrict__ x,
                   const int* __restrict__ xi) {
    __shared__ float xs[NN];      // xs[m] = x[b, m, p]
    __shared__ int t_s;

    const int b   = blockIdx.x;
    const int p   = blockIdx.y;
    const int tid = threadIdx.x;
    const int lane = tid & 31;
    const int wid  = tid >> 5;    // 0..3

    if (tid == 0) t_s = xi[b * PP + p];
    if (tid < NN) xs[tid] = x[(size_t)b * (NN * PP) + tid * PP + p];
    __syncthreads();

    const float* wrow = g_w + (size_t)t_s * KDIM;
    const float2 xp = ((const float2*)xs)[lane];   // m = 2*lane, 2*lane+1

#pragma unroll
    for (int nn = 0; nn < 16; nn++) {
        const int n = wid * 16 + nn;
        const float2 wv = ((const float2*)(wrow + n * 64))[lane];
        float v = wv.x * xp.x + wv.y * xp.y;
        v += __shfl_xor_sync(0xffffffffu, v, 16);
        v += __shfl_xor_sync(0xffffffffu, v, 8);
        v += __shfl_xor_sync(0xffffffffu, v, 4);
        v += __shfl_xor_sync(0xffffffffu, v, 2);
        v += __shfl_xor_sync(0xffffffffu, v, 1);
        if (lane == 0) g_Zp[p][b * NN + n] = v;
    }
}

// ---------------------------------------------------------------------------
// Kernel 3b: Z = sum over the 32 per-p partials (deterministic)
// ---------------------------------------------------------------------------
__global__ __launch_bounds__(256, 4)
void zfinal_kernel(float* __restrict__ Z) {
    const int i = blockIdx.x * 256 + threadIdx.x;   // 0..4095
    float s = 0.f;
#pragma unroll
    for (int p = 0; p < PP; p++) s += g_Zp[p][i];
    Z[i] = s;
}

// ---------------------------------------------------------------------------
// Launch. Inputs: x [B,N,P] f32, x_i [B,P] i32, g [4096,4096] f32,
//                 weights [4096,512] f32.  Output: Z (4096 f32) then F.
// ---------------------------------------------------------------------------
extern "C" void kernel_launch(void* const* d_in, const int* in_sizes, int n_in,
                              void* d_out, int out_size) {
    const float* x   = (const float*)d_in[0];
    const int*   xi  = (const int*)d_in[1];
    const float* g   = (const float*)d_in[2];
    const float* wts = (const float*)d_in[3];

    float* Z = (float*)d_out;
    float* F = (float*)d_out + NN * NN;

    cudaFuncSetAttribute(mma_gemm_kernel,
                         cudaFuncAttributeMaxDynamicSharedMemorySize, SMEM_T);

    split_g_kernel<<<dim3(KDIM / 32, KDIM / 128), 256>>>(g);
    split_w_kernel<<<dim3(KDIM / 32, NCOLS / 128), 256>>>(wts);

    mma_gemm_kernel<<<dim3(NCOLS / 128, KDIM / 128), 256, SMEM_T>>>(F);

    gather_kernel<<<dim3(BB, PP), 128>>>(x, xi);
    zfinal_kernel<<<(BB * NN) / 256, 256>>>(Z);
}

// round 13
// speedup vs baseline: 2.0895x; 1.0446x over previous
#include <cuda_runtime.h>
#include <cuda_fp16.h>
#include <cstdint>

// Problem constants
#define NN      64
#define TT      512
#define BB      64
#define PP      32
#define KDIM    4096        // N*N
#define NCOLS   512         // T

// ---------------------------------------------------------------------------
// Device scratch (static — allocation-free per harness rules)
// g_w layout: g_w[t*4096 + i*64 + j]
// Operands stored TILED fp16: tile = [128 rows x 32 k] = 8 KB contiguous,
// SW64-swizzled; GEMM fetches a stage with 2 TMA bulk copies.
// ---------------------------------------------------------------------------
__device__ float g_w[TT * KDIM];
__device__ __half g_f16_t[(size_t)KDIM * KDIM];        // 33.5 MB tiled
__device__ __half w2t_f16_t[(size_t)NCOLS * KDIM];     // 4 MB tiled

// ---------------------------------------------------------------------------
// PTX helpers (baseline sm_90-level PTX, valid on plain sm_103 target)
// ---------------------------------------------------------------------------
__device__ __forceinline__ uint32_t smem_u32(const void* p) {
    uint32_t a;
    asm("{ .reg .u64 t; cvta.to.shared.u64 t, %1; cvt.u32.u64 %0, t; }"
        : "=r"(a) : "l"(p));
    return a;
}

__device__ __forceinline__ void cp_bulk8k(uint32_t dst, const void* src,
                                          uint32_t mbar) {
    asm volatile(
        "cp.async.bulk.shared::cluster.global.mbarrier::complete_tx::bytes "
        "[%0], [%1], %2, [%3];"
        :: "r"(dst), "l"(src), "r"(8192u), "r"(mbar) : "memory");
}

__device__ __forceinline__ void mbar_init(uint32_t mbar, uint32_t cnt) {
    asm volatile("mbarrier.init.shared.b64 [%0], %1;" :: "r"(mbar), "r"(cnt)
                 : "memory");
}

__device__ __forceinline__ void mbar_expect_tx(uint32_t mbar, uint32_t bytes) {
    asm volatile("mbarrier.arrive.expect_tx.shared.b64 _, [%0], %1;"
                 :: "r"(mbar), "r"(bytes) : "memory");
}

__device__ __forceinline__ void mbar_wait(uint32_t mbar, uint32_t parity) {
    asm volatile(
        "{\n\t"
        ".reg .pred P1;\n\t"
        "WAIT_LOOP_%=:\n\t"
        "mbarrier.try_wait.parity.acquire.cta.shared::cta.b64 P1, [%0], %1, 0x989680;\n\t"
        "@P1 bra.uni WAIT_DONE_%=;\n\t"
        "bra.uni WAIT_LOOP_%=;\n\t"
        "WAIT_DONE_%=:\n\t"
        "}"
        :: "r"(mbar), "r"(parity) : "memory");
}

#define LDSM4(r, addr)                                                         \
    asm volatile("ldmatrix.sync.aligned.m8n8.x4.shared.b16 "                   \
                 "{%0,%1,%2,%3}, [%4];"                                        \
                 : "=r"((r)[0]), "=r"((r)[1]), "=r"((r)[2]), "=r"((r)[3])      \
                 : "r"(addr))

#define MMA16816F16(c, a, b0, b1)                                              \
    asm volatile("mma.sync.aligned.m16n8k16.row.col.f32.f16.f16.f32 "          \
                 "{%0,%1,%2,%3},{%4,%5,%6,%7},{%8,%9},{%0,%1,%2,%3};"          \
                 : "+f"((c)[0]), "+f"((c)[1]), "+f"((c)[2]), "+f"((c)[3])      \
                 : "r"((a)[0]), "r"((a)[1]), "r"((a)[2]), "r"((a)[3]),         \
                   "r"(b0), "r"(b1))

// SW64 swizzle for 64-byte rows (conflict-free ldmatrix, proven)
__device__ __forceinline__ uint32_t swz64(uint32_t off) {
    return off ^ ((off >> 3) & 0x30);
}

__device__ __forceinline__ uint32_t pk_h2(float x, float y) {
    return ((uint32_t)__half_as_ushort(__float2half_rn(y)) << 16) |
           __half_as_ushort(__float2half_rn(x));
}
__device__ __forceinline__ uint4 pack8_f16(const float4& u, const float4& v) {
    uint4 h;
    h.x = pk_h2(u.x, u.y); h.y = pk_h2(u.z, u.w);
    h.z = pk_h2(v.x, v.y); h.w = pk_h2(v.z, v.w);
    return h;
}

// ---------------------------------------------------------------------------
// Kernel 0a: convert g (fp32, row-major) to fp16 tiled+swizzled.
// ---------------------------------------------------------------------------
__global__ __launch_bounds__(256, 4)
void split_g_kernel(const float* __restrict__ g) {
    const int kc = blockIdx.x;
    const int bm = blockIdx.y;
    const int tid = threadIdx.x;
    const size_t tbase = (size_t)(bm * 128 + kc) * 8192;
#pragma unroll
    for (int j = 0; j < 2; j++) {
        const int id  = tid + j * 256;
        const int row = id >> 2;
        const int c16 = id & 3;
        const float* p = g + (size_t)(bm * 128 + row) * KDIM + kc * 32 + c16 * 8;
        const float4 v0 = *(const float4*)p;
        const float4 v1 = *(const float4*)(p + 4);
        const uint4 h = pack8_f16(v0, v1);
        const uint32_t off = swz64((uint32_t)(row * 64 + c16 * 16));
        *(uint4*)((char*)g_f16_t + tbase + off) = h;
    }
}

// ---------------------------------------------------------------------------
// Kernel 0b: weights [K=4096, T=512] -> (w^2)^T tiled fp16.
// ---------------------------------------------------------------------------
__global__ __launch_bounds__(256, 2)
void split_w_kernel(const float* __restrict__ w) {
    __shared__ float tile[128][33];   // [t_local][k_local]
    const int kc = blockIdx.x;
    const int bn = blockIdx.y;
    const int tid = threadIdx.x;

#pragma unroll
    for (int j = 0; j < 16; j++) {
        const int id = tid + j * 256;
        const int kl = id >> 7;
        const int tl = id & 127;
        const float v = w[(size_t)(kc * 32 + kl) * NCOLS + bn * 128 + tl];
        tile[tl][kl] = v * v;
    }
    __syncthreads();

    const size_t tbase = (size_t)(bn * 128 + kc) * 8192;
#pragma unroll
    for (int j = 0; j < 2; j++) {
        const int id = tid + j * 256;
        const int r  = id >> 2;
        const int c16 = id & 3;
        float4 u, v;
        u.x = tile[r][c16 * 8 + 0]; u.y = tile[r][c16 * 8 + 1];
        u.z = tile[r][c16 * 8 + 2]; u.w = tile[r][c16 * 8 + 3];
        v.x = tile[r][c16 * 8 + 4]; v.y = tile[r][c16 * 8 + 5];
        v.z = tile[r][c16 * 8 + 6]; v.w = tile[r][c16 * 8 + 7];
        const uint4 h = pack8_f16(u, v);
        const uint32_t off = swz64((uint32_t)(r * 64 + c16 * 16));
        *(uint4*)((char*)w2t_f16_t + tbase + off) = h;
    }
}

// ---------------------------------------------------------------------------
// Kernel 1: F = g @ weights^2, single-pass fp16 HMMA, TMA loads, fused
// row-softmax epilogue with smem-staged coalesced g_w stores.
//   Grid (4, 32). CTA tile 128x128 over K=4096. 256 threads = 8 warps
//   (2M x 4N), warp tile 64x32. 8-slot TMA ring, 128 KB smem.
// ---------------------------------------------------------------------------
#define ATILE   8192
#define STAGE_B (2 * ATILE)                // 16 KB
#define NSLOT   8
#define SMEM_T  (NSLOT * STAGE_B)          // 128 KB
#define KSTAGES (KDIM / 32)                // 128

__global__ __launch_bounds__(256, 1)
void mma_gemm_kernel(float* __restrict__ F) {
    extern __shared__ char smem[];
    __shared__ uint64_t mbars[NSLOT];
    const uint32_t sb = smem_u32(smem);
    const uint32_t mb0 = smem_u32(&mbars[0]);
    const int tid  = threadIdx.x;
    const int lane = tid & 31;
    const int wid  = tid >> 5;
    const int bn = blockIdx.x;             // 0..3
    const int bm = blockIdx.y;             // 0..31
    const int wm = wid >> 2;               // 0..1 -> row offset wm*64
    const int wn = wid & 3;                // 0..3 -> col offset wn*32

    const char* Ag = (const char*)g_f16_t   + (size_t)(bm * 128) * 8192;
    const char* Bg = (const char*)w2t_f16_t + (size_t)(bn * 128) * 8192;

    if (tid == 0) {
#pragma unroll
        for (int i = 0; i < NSLOT; i++) mbar_init(mb0 + i * 8, 1);
    }
    __syncthreads();

    auto issue = [&](int s) {
        const int slot = s & (NSLOT - 1);
        const uint32_t mb  = mb0 + slot * 8;
        const uint32_t dst = sb + slot * STAGE_B;
        mbar_expect_tx(mb, STAGE_B);
        const size_t to = (size_t)s * 8192;
        cp_bulk8k(dst,         Ag + to, mb);
        cp_bulk8k(dst + ATILE, Bg + to, mb);
    };

    if (tid == 0) {
#pragma unroll
        for (int i = 0; i < NSLOT - 1; i++) issue(i);
    }

    float c[4][4][4];
#pragma unroll
    for (int mt = 0; mt < 4; mt++)
#pragma unroll
        for (int nt = 0; nt < 4; nt++)
#pragma unroll
            for (int q = 0; q < 4; q++) c[mt][nt][q] = 0.f;

    const int rA    = lane & 15;
    const int kHalf = (lane >> 4) << 4;

    for (int s = 0; s < KSTAGES; s++) {
        const int slot = s & (NSLOT - 1);
        if (tid == 0 && s + NSLOT - 1 < KSTAGES) issue(s + NSLOT - 1);

        mbar_wait(mb0 + slot * 8, (s >> 3) & 1);

        const uint32_t ab = sb + slot * STAGE_B;
        const uint32_t bb = ab + ATILE;

#pragma unroll
        for (int kk = 0; kk < 2; kk++) {
            const int kb = kk * 32 + kHalf;
            uint32_t ahr[4][4];
#pragma unroll
            for (int mt = 0; mt < 4; mt++) {
                const int row = wm * 64 + mt * 16 + rA;
                const uint32_t off = swz64((uint32_t)(row * 64 + kb));
                LDSM4(ahr[mt], ab + off);
            }
#pragma unroll
            for (int gg = 0; gg < 2; gg++) {
                uint32_t bhr[4];
                const int row = wn * 32 + gg * 16 + rA;
                const uint32_t off = swz64((uint32_t)(row * 64 + kb));
                LDSM4(bhr, bb + off);
#pragma unroll
                for (int mt = 0; mt < 4; mt++)
#pragma unroll
                    for (int h = 0; h < 2; h++)
                        MMA16816F16(c[mt][gg * 2 + h], ahr[mt], bhr[h], bhr[h + 2]);
            }
        }
        __syncthreads();     // all warps done reading slot before reuse
    }

    // ---- epilogue 1: write raw F (row-major [4096, 512]) ----
    const int r_lo = lane >> 2;
    const int c_lo = (lane & 3) * 2;
#pragma unroll
    for (int mt = 0; mt < 4; mt++) {
        const int row0 = bm * 128 + wm * 64 + mt * 16 + r_lo;
#pragma unroll
        for (int nt = 0; nt < 4; nt++) {
            const int col = bn * 128 + wn * 32 + nt * 8 + c_lo;
            float2 v0 = make_float2(c[mt][nt][0], c[mt][nt][1]);
            float2 v1 = make_float2(c[mt][nt][2], c[mt][nt][3]);
            *(float2*)(F + (size_t)row0 * NCOLS + col)       = v0;
            *(float2*)(F + (size_t)(row0 + 8) * NCOLS + col) = v1;
        }
    }

    // ---- epilogue 2: fused softmax over the warp's 64 rows, per column ----
    float mA[4], mB[4], sA[4], sB[4];
#pragma unroll
    for (int nt = 0; nt < 4; nt++) {
        float ma = -3.402823466e+38f, mb = ma;
#pragma unroll
        for (int mt = 0; mt < 4; mt++) {
            ma = fmaxf(ma, fmaxf(c[mt][nt][0], c[mt][nt][2]));
            mb = fmaxf(mb, fmaxf(c[mt][nt][1], c[mt][nt][3]));
        }
        ma = fmaxf(ma, __shfl_xor_sync(0xffffffffu, ma, 4));
        ma = fmaxf(ma, __shfl_xor_sync(0xffffffffu, ma, 8));
        ma = fmaxf(ma, __shfl_xor_sync(0xffffffffu, ma, 16));
        mb = fmaxf(mb, __shfl_xor_sync(0xffffffffu, mb, 4));
        mb = fmaxf(mb, __shfl_xor_sync(0xffffffffu, mb, 8));
        mb = fmaxf(mb, __shfl_xor_sync(0xffffffffu, mb, 16));
        mA[nt] = ma; mB[nt] = mb;
    }
#pragma unroll
    for (int nt = 0; nt < 4; nt++) {
        float sa = 0.f, sbv = 0.f;
#pragma unroll
        for (int mt = 0; mt < 4; mt++) {
            c[mt][nt][0] = __expf(c[mt][nt][0] - mA[nt]);
            c[mt][nt][2] = __expf(c[mt][nt][2] - mA[nt]);
            c[mt][nt][1] = __expf(c[mt][nt][1] - mB[nt]);
            c[mt][nt][3] = __expf(c[mt][nt][3] - mB[nt]);
            sa  += c[mt][nt][0] + c[mt][nt][2];
            sbv += c[mt][nt][1] + c[mt][nt][3];
        }
        sa  += __shfl_xor_sync(0xffffffffu, sa, 4);
        sa  += __shfl_xor_sync(0xffffffffu, sa, 8);
        sa  += __shfl_xor_sync(0xffffffffu, sa, 16);
        sbv += __shfl_xor_sync(0xffffffffu, sbv, 4);
        sbv += __shfl_xor_sync(0xffffffffu, sbv, 8);
        sbv += __shfl_xor_sync(0xffffffffu, sbv, 16);
        sA[nt] = 1.f / sa; sB[nt] = 1.f / sbv;
    }

    // ---- epilogue 3: stage w through (now idle) pipeline smem, then store
    //      coalesced. Warp layout sw[tl*72 + j], stride 72 -> <=2-way banks.
    float* sw = (float*)smem + wid * 2304;   // 2304 floats = 9216 B per warp
#pragma unroll
    for (int nt = 0; nt < 4; nt++) {
        const int tl = nt * 8 + c_lo;         // even 0..30
#pragma unroll
        for (int mt = 0; mt < 4; mt++) {
            const int j0 = mt * 16 + r_lo;
            sw[tl * 72 + j0]           = c[mt][nt][0] * sA[nt];
            sw[tl * 72 + j0 + 8]       = c[mt][nt][2] * sA[nt];
            sw[(tl + 1) * 72 + j0]     = c[mt][nt][1] * sB[nt];
            sw[(tl + 1) * 72 + j0 + 8] = c[mt][nt][3] * sB[nt];
        }
    }
    __syncwarp();
    // w: g_w[t*4096 + i*64 + j], i = 2*bm + wm (one i-group per warp)
    const int ibase = (2 * bm + wm) * 64;
    const int tbase = bn * 128 + wn * 32;
#pragma unroll
    for (int tl = 0; tl < 32; tl++) {
        const float v0 = sw[tl * 72 + lane];
        const float v1 = sw[tl * 72 + 32 + lane];
        float* dst = g_w + (size_t)(tbase + tl) * KDIM + ibase;
        dst[lane]      = v0;
        dst[32 + lane] = v1;
    }
}

// ---------------------------------------------------------------------------
// Kernel 3: gather, one fat block per b (writes Z directly, no zfinal).
// 512 threads = 16 warps; warp handles p = {wid, wid+16}.
// Per (p, n-pair): lanes 0-15 cover n (m via float4), lanes 16-31 cover n+1;
// one coalesced 512B LDG.128 per warp-iteration; 4-deep shfl reduce.
// Partials in smem, fixed two-stage tree sum (deterministic) -> Z.
// ---------------------------------------------------------------------------
__global__ __launch_bounds__(512, 1)
void gather_kernel(const float* __restrict__ x,
                   const int* __restrict__ xi,
                   float* __restrict__ Z) {
    __shared__ float xs[PP * 68];       // xs[p*68 + m] = x[b, m, p]
    __shared__ int   ti[PP];
    __shared__ float part[PP * NN];     // part[p*64 + n]
    __shared__ float ps2[8 * NN];       // stage-2 partials

    const int b    = blockIdx.x;
    const int tid  = threadIdx.x;
    const int lane = tid & 31;
    const int wid  = tid >> 5;          // 0..15

    if (tid < PP) ti[tid] = xi[b * PP + tid];
    {
        // x[b] is 2048 floats = 512 float4; thread tid takes one.
        const float4 v = ((const float4*)(x + (size_t)b * NN * PP))[tid];
        const int m  = tid >> 3;        // 0..63
        const int p0 = (tid & 7) * 4;   // 0,4,...,28
        xs[(p0 + 0) * 68 + m] = v.x;
        xs[(p0 + 1) * 68 + m] = v.y;
        xs[(p0 + 2) * 68 + m] = v.z;
        xs[(p0 + 3) * 68 + m] = v.w;
    }
    __syncthreads();

    const int m4 = lane & 15;           // float4 index over m
    const int nh = lane >> 4;           // 0/1: which n of the pair
#pragma unroll
    for (int pp = 0; pp < 2; pp++) {
        const int p = wid + pp * 16;
        const int t = ti[p];
        const float* wrow = g_w + (size_t)t * KDIM;
        const float4 xp = *(const float4*)&xs[p * 68 + m4 * 4];
#pragma unroll 4
        for (int nn = 0; nn < 32; nn++) {
            const int n = nn * 2 + nh;
            const float4 wv = *(const float4*)(wrow + n * 64 + m4 * 4);
            float v = wv.x * xp.x + wv.y * xp.y + wv.z * xp.z + wv.w * xp.w;
            v += __shfl_xor_sync(0xffffffffu, v, 8);
            v += __shfl_xor_sync(0xffffffffu, v, 4);
            v += __shfl_xor_sync(0xffffffffu, v, 2);
            v += __shfl_xor_sync(0xffffffffu, v, 1);
            if (m4 == 0) part[p * 64 + n] = v;
        }
    }
    __syncthreads();

    // stage-2: thread (q = tid/64 in 0..7, n = tid%64) sums 4 p's
    {
        const int n = tid & 63;
        const int q = tid >> 6;
        ps2[q * 64 + n] = part[(q * 4 + 0) * 64 + n]
                        + part[(q * 4 + 1) * 64 + n]
                        + part[(q * 4 + 2) * 64 + n]
                        + part[(q * 4 + 3) * 64 + n];
    }
    __syncthreads();

    if (tid < NN) {
        float s = 0.f;
#pragma unroll
        for (int q = 0; q < 8; q++) s += ps2[q * 64 + tid];
        Z[b * NN + tid] = s;
    }
}

// ---------------------------------------------------------------------------
// Launch. Inputs: x [B,N,P] f32, x_i [B,P] i32, g [4096,4096] f32,
//                 weights [4096,512] f32.  Output: Z (4096 f32) then F.
// ---------------------------------------------------------------------------
extern "C" void kernel_launch(void* const* d_in, const int* in_sizes, int n_in,
                              void* d_out, int out_size) {
    const float* x   = (const float*)d_in[0];
    const int*   xi  = (const int*)d_in[1];
    const float* g   = (const float*)d_in[2];
    const float* wts = (const float*)d_in[3];

    float* Z = (float*)d_out;
    float* F = (float*)d_out + NN * NN;

    cudaFuncSetAttribute(mma_gemm_kernel,
                         cudaFuncAttributeMaxDynamicSharedMemorySize, SMEM_T);

    split_g_kernel<<<dim3(KDIM / 32, KDIM / 128), 256>>>(g);
    split_w_kernel<<<dim3(KDIM / 32, NCOLS / 128), 256>>>(wts);

    mma_gemm_kernel<<<dim3(NCOLS / 128, KDIM / 128), 256, SMEM_T>>>(F);

    gather_kernel<<<BB, 512>>>(x, xi, Z);
}